// round 3
// baseline (speedup 1.0000x reference)
#include <cuda_runtime.h>

#define HID 128
#define OUT_COLS 264
#define MAXN 50176

typedef unsigned long long ull;

// Scratch (no allocation allowed)
__device__ float g_Pn[(size_t)MAXN * HID];   // x_nbr  @ W1[:128]
__device__ float g_Pa[(size_t)MAXN * HID];   // x_agent@ W1[128:] + b1
__device__ int   g_idx64;

// ---- packed fp32x2 helpers (sm_103a) --------------------------------------
__device__ __forceinline__ ull pack2(float lo, float hi) {
    ull r; asm("mov.b64 %0, {%1,%2};" : "=l"(r) : "f"(lo), "f"(hi)); return r;
}
__device__ __forceinline__ void ffma2(ull& d, ull a, ull b) {
    asm("fma.rn.f32x2 %0, %1, %2, %0;" : "+l"(d) : "l"(a), "l"(b));
}
__device__ __forceinline__ float2 unpack2(ull v) {
    float2 r; asm("mov.b64 {%0,%1}, %2;" : "=f"(r.x), "=f"(r.y) : "l"(v)); return r;
}

// ---------------------------------------------------------------------------
__global__ void detect_idx_kernel(const int* __restrict__ eslot_words) {
    g_idx64 = (eslot_words[1] != 1) ? 1 : 0;
}

// Zero only out[:, 128:256] — cols 0..127 fully covered by edge writes
// (slot = tile(arange(16))), cols 256..263 by own_kernel.
__global__ void zero_mid_kernel(float* __restrict__ out, int N) {
    int total = N * 32;                       // 32 float4 per row
    float4 z = make_float4(0.f, 0.f, 0.f, 0.f);
    for (int i = blockIdx.x * blockDim.x + threadIdx.x; i < total;
         i += gridDim.x * blockDim.x) {
        int row = i >> 5, c4 = i & 31;
        *(float4*)(out + (size_t)row * OUT_COLS + 128 + c4 * 4) = z;
    }
}

// ---------------------------------------------------------------------------
// P[N,128] = X[N,128] @ W[128,128] (+bias). gridDim.y selects (x_nbr|x_agent).
// Block 256 thr, tile 32 rows x 128 cols, thread 4x4, k-pair f32x2 packing.
__global__ __launch_bounds__(256) void gemm_x128(
    const float* __restrict__ X0, const float* __restrict__ X1,
    const float* __restrict__ W1, const float* __restrict__ b1,
    int N0, int N1)
{
    extern __shared__ float sm[];
    float* ws = sm;                  // [128][128]
    float* xs = sm + 128 * 128;      // [32][132]
    const int t = threadIdx.x;
    const int sel = blockIdx.y;
    const float* __restrict__ X = sel ? X1 : X0;
    const float* __restrict__ W = sel ? (W1 + 128 * 128) : W1;
    float* __restrict__ P = sel ? g_Pa : g_Pn;
    const int N = sel ? N1 : N0;
    const int row0 = blockIdx.x * 32;
    if (row0 >= N) return;           // uniform per block

    // stage W (4096 float4)
    {
        const float4* W4 = (const float4*)W;
        float4* ws4 = (float4*)ws;
#pragma unroll
        for (int i = 0; i < 16; i++) ws4[t + 256 * i] = W4[t + 256 * i];
    }
    // stage X tile: 32 rows x 32 float4
#pragma unroll
    for (int ii = 0; ii < 4; ii++) {
        int i = t + 256 * ii;
        int r = i >> 5, c4 = i & 31;
        float4 v = make_float4(0.f, 0.f, 0.f, 0.f);
        int gr = row0 + r;
        if (gr < N) v = ((const float4*)X)[(size_t)gr * 32 + c4];
        float* xr = xs + r * 132 + c4 * 4;
        xr[0] = v.x; xr[1] = v.y; xr[2] = v.z; xr[3] = v.w;
    }
    __syncthreads();

    const int c  = (t & 31) * 4;     // output cols c..c+3
    const int r0 = (t >> 5) * 4;     // output rows r0..r0+3
    ull acc[4][4];
#pragma unroll
    for (int i = 0; i < 4; i++)
#pragma unroll
        for (int j = 0; j < 4; j++) acc[i][j] = 0ull;

#pragma unroll 8
    for (int kp = 0; kp < 64; kp++) {
        const int k = kp * 2;
        ull a2[4];
#pragma unroll
        for (int i = 0; i < 4; i++)                 // broadcast LDS.64
            a2[i] = *(const ull*)(xs + (r0 + i) * 132 + k);
        float4 br0 = *(const float4*)(ws + k * 128 + c);
        float4 br1 = *(const float4*)(ws + (k + 1) * 128 + c);
        ull b2[4] = { pack2(br0.x, br1.x), pack2(br0.y, br1.y),
                      pack2(br0.z, br1.z), pack2(br0.w, br1.w) };
#pragma unroll
        for (int i = 0; i < 4; i++)
#pragma unroll
            for (int j = 0; j < 4; j++) ffma2(acc[i][j], a2[i], b2[j]);
    }

    float4 bv = make_float4(0.f, 0.f, 0.f, 0.f);
    if (sel) bv = *(const float4*)(b1 + c);
#pragma unroll
    for (int i = 0; i < 4; i++) {
        int gr = row0 + r0 + i;
        if (gr < N) {
            float2 u0 = unpack2(acc[i][0]), u1 = unpack2(acc[i][1]);
            float2 u2 = unpack2(acc[i][2]), u3 = unpack2(acc[i][3]);
            *(float4*)(P + (size_t)gr * 128 + c) =
                make_float4(u0.x + u0.y + bv.x, u1.x + u1.y + bv.y,
                            u2.x + u2.y + bv.z, u3.x + u3.y + bv.w);
        }
    }
}

// ---------------------------------------------------------------------------
__global__ void own_kernel(const float* __restrict__ xa,
                           const float* __restrict__ Wa,
                           const float* __restrict__ ba,
                           float* __restrict__ out, int N)
{
    __shared__ float ws[128 * 8];
    __shared__ float bs[8];
    int t = threadIdx.x;
    for (int i = t; i < 1024; i += blockDim.x) ws[i] = Wa[i];
    if (t < 8) bs[t] = ba[t];
    __syncthreads();

    int idx = blockIdx.x * blockDim.x + t;
    int row = idx >> 3, c = idx & 7;
    if (row >= N) return;

    const float4* xr = (const float4*)(xa + (size_t)row * 128);
    float acc = bs[c];
#pragma unroll 8
    for (int kk = 0; kk < 32; kk++) {
        float4 a = xr[kk];
        int k = kk * 4;
        acc += a.x * ws[(k + 0) * 8 + c];
        acc += a.y * ws[(k + 1) * 8 + c];
        acc += a.z * ws[(k + 2) * 8 + c];
        acc += a.w * ws[(k + 3) * 8 + c];
    }
    out[(size_t)row * OUT_COLS + 256 + c] = acc;
}

// ---------------------------------------------------------------------------
// scores = relu(Pn[src] + Pa[dst]) @ W2 + b2 -> out[dst, slot*8 .. +8]
// W2 pre-packed into k-pair u64 table; matvec in f32x2.
__global__ __launch_bounds__(256) void edge_kernel(
    const float* __restrict__ W2, const float* __restrict__ b2,
    const void* __restrict__ esrc, const void* __restrict__ edst,
    const void* __restrict__ eslot,
    float* __restrict__ out, int E)
{
    __shared__ ull w2p[64][8];       // [k-pair][col] = (W2[2kp][c], W2[2kp+1][c])
    __shared__ float b2s[8];
    int t = threadIdx.x;
    if (t < 8) b2s[t] = b2[t];
    for (int i = t; i < 512; i += 256) {
        int kp = i >> 3, c = i & 7;
        w2p[kp][c] = pack2(W2[(2 * kp) * 8 + c], W2[(2 * kp + 1) * 8 + c]);
    }
    __syncthreads();

    int e = blockIdx.x * 256 + t;
    if (e >= E) return;

    long long src, dst, slot;
    if (g_idx64) {
        src  = ((const long long*)esrc)[e];
        dst  = ((const long long*)edst)[e];
        slot = ((const long long*)eslot)[e];
    } else {
        src  = ((const int*)esrc)[e];
        dst  = ((const int*)edst)[e];
        slot = ((const int*)eslot)[e];
    }

    const float4* __restrict__ pn = (const float4*)(g_Pn + (size_t)src * 128);
    const float4* __restrict__ pa = (const float4*)(g_Pa + (size_t)dst * 128);

    ull acc[8];
#pragma unroll
    for (int c = 0; c < 8; c++) acc[c] = pack2(b2s[c], 0.f);

#pragma unroll 8
    for (int kk = 0; kk < 32; kk++) {        // 4 k's per iter = 2 k-pairs
        float4 a = pn[kk];
        float4 b = pa[kk];
        ull v01 = pack2(fmaxf(a.x + b.x, 0.f), fmaxf(a.y + b.y, 0.f));
        ull v23 = pack2(fmaxf(a.z + b.z, 0.f), fmaxf(a.w + b.w, 0.f));
        const int kp = kk * 2;
        const ulonglong2* w0 = (const ulonglong2*)&w2p[kp][0];
        const ulonglong2* w1 = (const ulonglong2*)&w2p[kp + 1][0];
#pragma unroll
        for (int q = 0; q < 4; q++) {        // cols 2q, 2q+1
            ulonglong2 wA = w0[q];
            ffma2(acc[2 * q],     v01, wA.x);
            ffma2(acc[2 * q + 1], v01, wA.y);
        }
#pragma unroll
        for (int q = 0; q < 4; q++) {
            ulonglong2 wB = w1[q];
            ffma2(acc[2 * q],     v23, wB.x);
            ffma2(acc[2 * q + 1], v23, wB.y);
        }
    }

    float r[8];
#pragma unroll
    for (int c = 0; c < 8; c++) { float2 u = unpack2(acc[c]); r[c] = u.x + u.y; }

    float* o = out + (size_t)dst * OUT_COLS + slot * 8;
    *(float4*)o       = make_float4(r[0], r[1], r[2], r[3]);
    *(float4*)(o + 4) = make_float4(r[4], r[5], r[6], r[7]);
}

// ---------------------------------------------------------------------------
extern "C" void kernel_launch(void* const* d_in, const int* in_sizes, int n_in,
                              void* d_out, int out_size)
{
    const float* x_nbr   = (const float*)d_in[0];
    const float* x_agent = (const float*)d_in[1];
    const float* W1      = (const float*)d_in[2];
    const float* b1      = (const float*)d_in[3];
    const float* W2      = (const float*)d_in[4];
    const float* b2      = (const float*)d_in[5];
    const float* Wa      = (const float*)d_in[6];
    const float* ba      = (const float*)d_in[7];
    const void*  esrc    = d_in[8];
    const void*  edst    = d_in[9];
    const void*  eslot   = d_in[10];

    int Nn = in_sizes[0] / HID;
    int Na = in_sizes[1] / HID;
    int E  = in_sizes[8];
    float* out = (float*)d_out;

    const int gemm_smem = (128 * 128 + 32 * 132) * (int)sizeof(float); // 82432 B
    cudaFuncSetAttribute(gemm_x128, cudaFuncAttributeMaxDynamicSharedMemorySize,
                         gemm_smem);

    detect_idx_kernel<<<1, 1>>>((const int*)eslot);

    zero_mid_kernel<<<400, 256>>>(out, Na);

    int Nmax = Nn > Na ? Nn : Na;
    dim3 ggrid((Nmax + 31) / 32, 2);
    gemm_x128<<<ggrid, 256, gemm_smem>>>(x_nbr, x_agent, W1, b1, Nn, Na);

    own_kernel<<<(Na * 8 + 255) / 256, 256>>>(x_agent, Wa, ba, out, Na);

    edge_kernel<<<(E + 255) / 256, 256>>>(W2, b2, esrc, edst, eslot, out, E);
}

// round 7
// speedup vs baseline: 1.0282x; 1.0282x over previous
#include <cuda_runtime.h>

#define HID 128
#define OUT_COLS 264
#define MAXN 50176

typedef unsigned long long ull;

__device__ float g_Pn[(size_t)MAXN * HID];   // x_nbr  @ W1[:128]
__device__ float g_Pa[(size_t)MAXN * HID];   // x_agent@ W1[128:] + b1
__device__ int   g_idx64;

// ---- packed fp32x2 helpers (sm_103a) --------------------------------------
__device__ __forceinline__ ull pack2(float lo, float hi) {
    ull r; asm("mov.b64 %0, {%1,%2};" : "=l"(r) : "f"(lo), "f"(hi)); return r;
}
__device__ __forceinline__ void ffma2(ull& d, ull a, ull b) {
    asm("fma.rn.f32x2 %0, %1, %2, %0;" : "+l"(d) : "l"(a), "l"(b));
}
__device__ __forceinline__ ull add2(ull a, ull b) {
    ull r; asm("add.rn.f32x2 %0, %1, %2;" : "=l"(r) : "l"(a), "l"(b)); return r;
}
__device__ __forceinline__ float2 unpack2(ull v) {
    float2 r; asm("mov.b64 {%0,%1}, %2;" : "=f"(r.x), "=f"(r.y) : "l"(v)); return r;
}

// ---------------------------------------------------------------------------
__global__ void detect_idx_kernel(const int* __restrict__ eslot_words) {
    g_idx64 = (eslot_words[1] != 1) ? 1 : 0;
}

// ---------------------------------------------------------------------------
// P[N,128] = X[N,128] @ W[128,128] (+bias). blockIdx.y selects input.
// Proven R1 body: 256 thr, 64 rows x 128 cols, W fully staged.
__global__ __launch_bounds__(256) void gemm_x128(
    const float* __restrict__ X0, const float* __restrict__ X1,
    const float* __restrict__ W1, const float* __restrict__ b1,
    int N0, int N1)
{
    extern __shared__ float sm[];
    float* ws = sm;                 // [128][128]
    float* xs = sm + 128 * 128;     // [64][132]
    const int t = threadIdx.x;
    const int sel = blockIdx.y;
    const float* __restrict__ X = sel ? X1 : X0;
    const float* __restrict__ W = sel ? (W1 + 128 * 128) : W1;
    float* __restrict__ P = sel ? g_Pa : g_Pn;
    const int N = sel ? N1 : N0;
    const int row0 = blockIdx.x * 64;
    if (row0 >= N) return;

    {
        const float4* W4 = (const float4*)W;
        float4* ws4 = (float4*)ws;
#pragma unroll
        for (int i = 0; i < 16; i++) ws4[t + 256 * i] = W4[t + 256 * i];
    }
    for (int i = t; i < 64 * 32; i += 256) {
        int r = i >> 5, c4 = i & 31;
        float4 v = make_float4(0.f, 0.f, 0.f, 0.f);
        int gr = row0 + r;
        if (gr < N) v = ((const float4*)X)[(size_t)gr * 32 + c4];
        float* xr = xs + r * 132 + c4 * 4;
        xr[0] = v.x; xr[1] = v.y; xr[2] = v.z; xr[3] = v.w;
    }
    __syncthreads();

    const int c  = (t & 31) * 4;
    const int r0 = (t >> 5) * 8;
    float bvx = 0.f, bvy = 0.f, bvz = 0.f, bvw = 0.f;
    if (sel) { float4 bb = *(const float4*)(b1 + c);
               bvx = bb.x; bvy = bb.y; bvz = bb.z; bvw = bb.w; }
    float acc[8][4];
#pragma unroll
    for (int i = 0; i < 8; i++) {
        acc[i][0] = bvx; acc[i][1] = bvy; acc[i][2] = bvz; acc[i][3] = bvw;
    }

#pragma unroll 8
    for (int k = 0; k < 128; k++) {
        float4 b = *(const float4*)(ws + k * 128 + c);
#pragma unroll
        for (int i = 0; i < 8; i++) {
            float a = xs[(r0 + i) * 132 + k];
            acc[i][0] += a * b.x;
            acc[i][1] += a * b.y;
            acc[i][2] += a * b.z;
            acc[i][3] += a * b.w;
        }
    }

#pragma unroll
    for (int i = 0; i < 8; i++) {
        int gr = row0 + r0 + i;
        if (gr < N)
            *(float4*)(P + (size_t)gr * 128 + c) =
                make_float4(acc[i][0], acc[i][1], acc[i][2], acc[i][3]);
    }
}

// ---------------------------------------------------------------------------
// Fused edge + zero(cols 128..256) + own(cols 256..264) kernel.
// Block 256 = 2 agents x 16 edges x 8 threads.
// Thread (eg, j): loads Pn/Pa float4 chunks {j, j+8, j+16, j+24} (each 8-lane
// group covers one contiguous 128B line per instr), handles k = 4(j+8i)+q,
// accumulates all 8 output cols in 4 f32x2 regs, 8-lane shuffle-reduce,
// thread j writes col j.
// Weight smem layout (INJECTIVE, conflict-free): for k = 4K+q, col c:
//   off(k,c) = K*36 + q*8 + c        (blocks of 32 values, stride 36)
// Read addr mod 32 = 4j + 8q + 2m -> 8 distinct bank-pairs across j=0..7;
// other edge groups in the warp issue identical addrs -> broadcast.
__global__ __launch_bounds__(256) void edge_fused_kernel(
    const float* __restrict__ W2, const float* __restrict__ b2,
    const float* __restrict__ Wa, const float* __restrict__ ba,
    const float* __restrict__ xa,
    const void* __restrict__ esrc, const void* __restrict__ edst,
    const void* __restrict__ eslot,
    float* __restrict__ out, int E, int Na)
{
    __shared__ float w2s[32 * 36];   // 1152
    __shared__ float was[32 * 36];

    const int t  = threadIdx.x;
    const int g  = t >> 7;          // agent within block
    const int at = t & 127;         // thread within agent
    const int eg = at >> 3;         // edge group 0..15
    const int j  = at & 7;          // col / chunk id

    // stage weights into stride-36 layout
    for (int i = t; i < 1024; i += 256) {
        int k = i >> 3, c = i & 7;
        int off = (k >> 2) * 36 + (k & 3) * 8 + c;
        w2s[off] = W2[i];
        was[off] = Wa[i];
    }
    __syncthreads();

    const long long agent = (long long)blockIdx.x * 2 + g;
    const bool agent_ok = (agent < Na);

    // zero out[:, 128:256) — one float per thread
    if (agent_ok)
        out[(size_t)agent * OUT_COLS + 128 + at] = 0.f;

    const long long e = agent * 16 + eg;
    if (e < E) {
        long long src, dst, slot;
        if (g_idx64) {
            src  = ((const long long*)esrc)[e];
            dst  = ((const long long*)edst)[e];
            slot = ((const long long*)eslot)[e];
        } else {
            src  = ((const int*)esrc)[e];
            dst  = ((const int*)edst)[e];
            slot = ((const int*)eslot)[e];
        }

        const float4* __restrict__ pr = (const float4*)(g_Pn + (size_t)src * 128);
        const float4* __restrict__ ar = (const float4*)(g_Pa + (size_t)dst * 128);
        float4 a4[4], c4[4];
#pragma unroll
        for (int i = 0; i < 4; i++) { a4[i] = pr[j + 8 * i]; c4[i] = ar[j + 8 * i]; }

        ull acc[4] = {0ull, 0ull, 0ull, 0ull};
#pragma unroll
        for (int i = 0; i < 4; i++) {
            float v0 = fmaxf(a4[i].x + c4[i].x, 0.f);
            float v1 = fmaxf(a4[i].y + c4[i].y, 0.f);
            float v2 = fmaxf(a4[i].z + c4[i].z, 0.f);
            float v3 = fmaxf(a4[i].w + c4[i].w, 0.f);
            const float* wb = w2s + (j + 8 * i) * 36;      // K = j + 8i
#pragma unroll
            for (int q = 0; q < 4; q++) {
                float v = (q == 0) ? v0 : (q == 1) ? v1 : (q == 2) ? v2 : v3;
                ull vv = pack2(v, v);
                const ull* w = (const ull*)(wb + q * 8);
                ffma2(acc[0], vv, w[0]);
                ffma2(acc[1], vv, w[1]);
                ffma2(acc[2], vv, w[2]);
                ffma2(acc[3], vv, w[3]);
            }
        }
        // reduce across the 8 lanes of the edge group
#pragma unroll
        for (int d = 1; d < 8; d <<= 1) {
#pragma unroll
            for (int p = 0; p < 4; p++)
                acc[p] = add2(acc[p], __shfl_xor_sync(0xffffffffu, acc[p], d));
        }
        float2 u = unpack2(acc[j >> 1]);
        float s = ((j & 1) ? u.y : u.x) + __ldg(b2 + j);
        out[(size_t)dst * OUT_COLS + slot * 8 + j] = s;
    }

    // own score: group eg==0 of each agent computes out[agent, 256:264]
    if (eg == 0 && agent_ok) {
        const float4* __restrict__ xr = (const float4*)(xa + (size_t)agent * 128);
        float4 a4[4];
#pragma unroll
        for (int i = 0; i < 4; i++) a4[i] = xr[j + 8 * i];

        ull acc[4] = {0ull, 0ull, 0ull, 0ull};
#pragma unroll
        for (int i = 0; i < 4; i++) {
            const float* wb = was + (j + 8 * i) * 36;
#pragma unroll
            for (int q = 0; q < 4; q++) {
                float v = (q == 0) ? a4[i].x : (q == 1) ? a4[i].y
                        : (q == 2) ? a4[i].z : a4[i].w;
                ull vv = pack2(v, v);
                const ull* w = (const ull*)(wb + q * 8);
                ffma2(acc[0], vv, w[0]);
                ffma2(acc[1], vv, w[1]);
                ffma2(acc[2], vv, w[2]);
                ffma2(acc[3], vv, w[3]);
            }
        }
#pragma unroll
        for (int d = 1; d < 8; d <<= 1) {
#pragma unroll
            for (int p = 0; p < 4; p++)
                acc[p] = add2(acc[p], __shfl_xor_sync(0x000000ffu, acc[p], d));
        }
        float2 u = unpack2(acc[j >> 1]);
        float s = ((j & 1) ? u.y : u.x) + __ldg(ba + j);
        out[(size_t)agent * OUT_COLS + 256 + j] = s;
    }
}

// ---------------------------------------------------------------------------
extern "C" void kernel_launch(void* const* d_in, const int* in_sizes, int n_in,
                              void* d_out, int out_size)
{
    const float* x_nbr   = (const float*)d_in[0];
    const float* x_agent = (const float*)d_in[1];
    const float* W1      = (const float*)d_in[2];
    const float* b1      = (const float*)d_in[3];
    const float* W2      = (const float*)d_in[4];
    const float* b2      = (const float*)d_in[5];
    const float* Wa      = (const float*)d_in[6];
    const float* ba      = (const float*)d_in[7];
    const void*  esrc    = d_in[8];
    const void*  edst    = d_in[9];
    const void*  eslot   = d_in[10];

    int Nn = in_sizes[0] / HID;
    int Na = in_sizes[1] / HID;
    int E  = in_sizes[8];
    float* out = (float*)d_out;

    const int gemm_smem = (128 * 128 + 64 * 132) * (int)sizeof(float); // 99328 B
    cudaFuncSetAttribute(gemm_x128, cudaFuncAttributeMaxDynamicSharedMemorySize,
                         gemm_smem);

    detect_idx_kernel<<<1, 1>>>((const int*)eslot);

    int Nmax = Nn > Na ? Nn : Na;
    dim3 ggrid((Nmax + 63) / 64, 2);
    gemm_x128<<<ggrid, 256, gemm_smem>>>(x_nbr, x_agent, W1, b1, Nn, Na);

    int units = (E + 15) / 16;              // edge groups of 16
    if (Na > units) units = Na;
    int blocks = (units + 1) / 2;
    edge_fused_kernel<<<blocks, 256>>>(W2, b2, Wa, ba, x_agent,
                                       esrc, edst, eslot, out, E, Na);
}

// round 8
// speedup vs baseline: 1.0957x; 1.0656x over previous
#include <cuda_runtime.h>
#include <cuda_fp16.h>

#define HID 128
#define OUT_COLS 264
#define MAXN 50176

typedef unsigned long long ull;
typedef unsigned int uint;

// fp16 storage of projected node features (half2 packed as uint), halves gather bytes
__device__ uint g_Pn[(size_t)MAXN * 64];   // x_nbr  @ W1[:128]
__device__ uint g_Pa[(size_t)MAXN * 64];   // x_agent@ W1[128:] + b1
__device__ int  g_idx64;

// ---- packed fp32x2 helpers (sm_103a) --------------------------------------
__device__ __forceinline__ ull pack2(float lo, float hi) {
    ull r; asm("mov.b64 %0, {%1,%2};" : "=l"(r) : "f"(lo), "f"(hi)); return r;
}
__device__ __forceinline__ void ffma2(ull& d, ull a, ull b) {
    asm("fma.rn.f32x2 %0, %1, %2, %0;" : "+l"(d) : "l"(a), "l"(b));
}
__device__ __forceinline__ ull add2(ull a, ull b) {
    ull r; asm("add.rn.f32x2 %0, %1, %2;" : "=l"(r) : "l"(a), "l"(b)); return r;
}
__device__ __forceinline__ float2 unpack2(ull v) {
    float2 r; asm("mov.b64 {%0,%1}, %2;" : "=f"(r.x), "=f"(r.y) : "l"(v)); return r;
}
__device__ __forceinline__ uint h2u(__half2 h) {
    return *reinterpret_cast<uint*>(&h);
}
__device__ __forceinline__ __half2 u2h(uint u) {
    return *reinterpret_cast<__half2*>(&u);
}

// ---------------------------------------------------------------------------
__global__ void detect_idx_kernel(const int* __restrict__ eslot_words) {
    g_idx64 = (eslot_words[1] != 1) ? 1 : 0;
}

// ---------------------------------------------------------------------------
// P[N,128] = X[N,128] @ W[128,128] (+bias), stored as half2. blockIdx.y selects.
__global__ __launch_bounds__(256) void gemm_x128(
    const float* __restrict__ X0, const float* __restrict__ X1,
    const float* __restrict__ W1, const float* __restrict__ b1,
    int N0, int N1)
{
    extern __shared__ float sm[];
    float* ws = sm;                 // [128][128]
    float* xs = sm + 128 * 128;     // [64][132]
    const int t = threadIdx.x;
    const int sel = blockIdx.y;
    const float* __restrict__ X = sel ? X1 : X0;
    const float* __restrict__ W = sel ? (W1 + 128 * 128) : W1;
    uint* __restrict__ P = sel ? g_Pa : g_Pn;
    const int N = sel ? N1 : N0;
    const int row0 = blockIdx.x * 64;
    if (row0 >= N) return;

    {
        const float4* W4 = (const float4*)W;
        float4* ws4 = (float4*)ws;
#pragma unroll
        for (int i = 0; i < 16; i++) ws4[t + 256 * i] = W4[t + 256 * i];
    }
    for (int i = t; i < 64 * 32; i += 256) {
        int r = i >> 5, c4 = i & 31;
        float4 v = make_float4(0.f, 0.f, 0.f, 0.f);
        int gr = row0 + r;
        if (gr < N) v = ((const float4*)X)[(size_t)gr * 32 + c4];
        float* xr = xs + r * 132 + c4 * 4;
        xr[0] = v.x; xr[1] = v.y; xr[2] = v.z; xr[3] = v.w;
    }
    __syncthreads();

    const int c  = (t & 31) * 4;
    const int r0 = (t >> 5) * 8;
    float bvx = 0.f, bvy = 0.f, bvz = 0.f, bvw = 0.f;
    if (sel) { float4 bb = *(const float4*)(b1 + c);
               bvx = bb.x; bvy = bb.y; bvz = bb.z; bvw = bb.w; }
    float acc[8][4];
#pragma unroll
    for (int i = 0; i < 8; i++) {
        acc[i][0] = bvx; acc[i][1] = bvy; acc[i][2] = bvz; acc[i][3] = bvw;
    }

#pragma unroll 8
    for (int k = 0; k < 128; k++) {
        float4 b = *(const float4*)(ws + k * 128 + c);
#pragma unroll
        for (int i = 0; i < 8; i++) {
            float a = xs[(r0 + i) * 132 + k];
            acc[i][0] += a * b.x;
            acc[i][1] += a * b.y;
            acc[i][2] += a * b.z;
            acc[i][3] += a * b.w;
        }
    }

#pragma unroll
    for (int i = 0; i < 8; i++) {
        int gr = row0 + r0 + i;
        if (gr < N) {
            uint u01 = h2u(__floats2half2_rn(acc[i][0], acc[i][1]));
            uint u23 = h2u(__floats2half2_rn(acc[i][2], acc[i][3]));
            *(uint2*)(P + (size_t)gr * 64 + (c >> 1)) = make_uint2(u01, u23);
        }
    }
}

// ---------------------------------------------------------------------------
// Fused edge + zero(cols 128..256) + own(cols 256..264).
// Block 256 = 2 agents x 16 edges x 8 threads. Thread (eg,j) handles
// k = 4(j+8i)+q (i=0..3, q=0..3); gathers are uint2 (4 halves = 8B/thread,
// 8-lane group covers 64B contiguous). Weights in fp32 smem, stride-36
// injective layout: off(4K+q, c) = K*36 + q*8 + c (verified R7).
__global__ __launch_bounds__(256) void edge_fused_kernel(
    const float* __restrict__ W2, const float* __restrict__ b2,
    const float* __restrict__ Wa, const float* __restrict__ ba,
    const float* __restrict__ xa,
    const void* __restrict__ esrc, const void* __restrict__ edst,
    const void* __restrict__ eslot,
    float* __restrict__ out, int E, int Na)
{
    __shared__ float w2s[32 * 36];
    __shared__ float was[32 * 36];

    const int t  = threadIdx.x;
    const int g  = t >> 7;
    const int at = t & 127;
    const int eg = at >> 3;
    const int j  = at & 7;

    for (int i = t; i < 1024; i += 256) {
        int k = i >> 3, c = i & 7;
        int off = (k >> 2) * 36 + (k & 3) * 8 + c;
        w2s[off] = W2[i];
        was[off] = Wa[i];
    }
    __syncthreads();

    const long long agent = (long long)blockIdx.x * 2 + g;
    const bool agent_ok = (agent < Na);

    if (agent_ok)
        out[(size_t)agent * OUT_COLS + 128 + at] = 0.f;

    const long long e = agent * 16 + eg;
    if (e < E) {
        long long src, dst, slot;
        if (g_idx64) {
            src  = ((const long long*)esrc)[e];
            dst  = ((const long long*)edst)[e];
            slot = ((const long long*)eslot)[e];
        } else {
            src  = ((const int*)esrc)[e];
            dst  = ((const int*)edst)[e];
            slot = ((const int*)eslot)[e];
        }

        const uint2* __restrict__ pr = (const uint2*)(g_Pn + (size_t)src * 64);
        const uint2* __restrict__ ar = (const uint2*)(g_Pa + (size_t)dst * 64);
        uint2 araw[4], craw[4];
#pragma unroll
        for (int i = 0; i < 4; i++) { araw[i] = pr[j + 8 * i]; craw[i] = ar[j + 8 * i]; }

        const __half2 z2 = __floats2half2_rn(0.f, 0.f);
        ull acc[4] = {0ull, 0ull, 0ull, 0ull};
#pragma unroll
        for (int i = 0; i < 4; i++) {
            __half2 h0 = __hmax2(__hadd2(u2h(araw[i].x), u2h(craw[i].x)), z2);
            __half2 h1 = __hmax2(__hadd2(u2h(araw[i].y), u2h(craw[i].y)), z2);
            float2 f0 = __half22float2(h0);   // k = 4(j+8i)+0, +1
            float2 f1 = __half22float2(h1);   // k = 4(j+8i)+2, +3
            const float* wb = w2s + (j + 8 * i) * 36;      // K = j + 8i
#pragma unroll
            for (int q = 0; q < 4; q++) {
                float v = (q == 0) ? f0.x : (q == 1) ? f0.y : (q == 2) ? f1.x : f1.y;
                ull vv = pack2(v, v);
                const ull* w = (const ull*)(wb + q * 8);
                ffma2(acc[0], vv, w[0]);
                ffma2(acc[1], vv, w[1]);
                ffma2(acc[2], vv, w[2]);
                ffma2(acc[3], vv, w[3]);
            }
        }
#pragma unroll
        for (int d = 1; d < 8; d <<= 1) {
#pragma unroll
            for (int p = 0; p < 4; p++)
                acc[p] = add2(acc[p], __shfl_xor_sync(0xffffffffu, acc[p], d));
        }
        float2 u = unpack2(acc[j >> 1]);
        float s = ((j & 1) ? u.y : u.x) + __ldg(b2 + j);
        out[(size_t)dst * OUT_COLS + slot * 8 + j] = s;
    }

    // own score (fp32 inputs, unchanged precision)
    if (eg == 0 && agent_ok) {
        const float4* __restrict__ xr = (const float4*)(xa + (size_t)agent * 128);
        float4 a4[4];
#pragma unroll
        for (int i = 0; i < 4; i++) a4[i] = xr[j + 8 * i];

        ull acc[4] = {0ull, 0ull, 0ull, 0ull};
#pragma unroll
        for (int i = 0; i < 4; i++) {
            const float* wb = was + (j + 8 * i) * 36;
#pragma unroll
            for (int q = 0; q < 4; q++) {
                float v = (q == 0) ? a4[i].x : (q == 1) ? a4[i].y
                        : (q == 2) ? a4[i].z : a4[i].w;
                ull vv = pack2(v, v);
                const ull* w = (const ull*)(wb + q * 8);
                ffma2(acc[0], vv, w[0]);
                ffma2(acc[1], vv, w[1]);
                ffma2(acc[2], vv, w[2]);
                ffma2(acc[3], vv, w[3]);
            }
        }
#pragma unroll
        for (int d = 1; d < 8; d <<= 1) {
#pragma unroll
            for (int p = 0; p < 4; p++)
                acc[p] = add2(acc[p], __shfl_xor_sync(0x000000ffu, acc[p], d));
        }
        float2 u = unpack2(acc[j >> 1]);
        float s = ((j & 1) ? u.y : u.x) + __ldg(ba + j);
        out[(size_t)agent * OUT_COLS + 256 + j] = s;
    }
}

// ---------------------------------------------------------------------------
extern "C" void kernel_launch(void* const* d_in, const int* in_sizes, int n_in,
                              void* d_out, int out_size)
{
    const float* x_nbr   = (const float*)d_in[0];
    const float* x_agent = (const float*)d_in[1];
    const float* W1      = (const float*)d_in[2];
    const float* b1      = (const float*)d_in[3];
    const float* W2      = (const float*)d_in[4];
    const float* b2      = (const float*)d_in[5];
    const float* Wa      = (const float*)d_in[6];
    const float* ba      = (const float*)d_in[7];
    const void*  esrc    = d_in[8];
    const void*  edst    = d_in[9];
    const void*  eslot   = d_in[10];

    int Nn = in_sizes[0] / HID;
    int Na = in_sizes[1] / HID;
    int E  = in_sizes[8];
    float* out = (float*)d_out;

    const int gemm_smem = (128 * 128 + 64 * 132) * (int)sizeof(float); // 99328 B
    cudaFuncSetAttribute(gemm_x128, cudaFuncAttributeMaxDynamicSharedMemorySize,
                         gemm_smem);

    detect_idx_kernel<<<1, 1>>>((const int*)eslot);

    int Nmax = Nn > Na ? Nn : Na;
    dim3 ggrid((Nmax + 63) / 64, 2);
    gemm_x128<<<ggrid, 256, gemm_smem>>>(x_nbr, x_agent, W1, b1, Nn, Na);

    int units = (E + 15) / 16;
    if (Na > units) units = Na;
    int blocks = (units + 1) / 2;
    edge_fused_kernel<<<blocks, 256>>>(W2, b2, Wa, ba, x_agent,
                                       esrc, edst, eslot, out, E, Na);
}

// round 11
// speedup vs baseline: 1.1133x; 1.0161x over previous
#include <cuda_runtime.h>
#include <cuda_fp16.h>

#define HID 128
#define OUT_COLS 264
#define MAXN 50176

typedef unsigned long long ull;
typedef unsigned int uint;

// fp16 storage of projected node features (half2 packed as uint)
__device__ uint g_Pn[(size_t)MAXN * 64];   // x_nbr  @ W1[:128]
__device__ uint g_Pa[(size_t)MAXN * 64];   // x_agent@ W1[128:] + b1

// ---- packed fp32x2 helpers (sm_103a) --------------------------------------
__device__ __forceinline__ ull pack2(float lo, float hi) {
    ull r; asm("mov.b64 %0, {%1,%2};" : "=l"(r) : "f"(lo), "f"(hi)); return r;
}
__device__ __forceinline__ void ffma2(ull& d, ull a, ull b) {
    asm("fma.rn.f32x2 %0, %1, %2, %0;" : "+l"(d) : "l"(a), "l"(b));
}
__device__ __forceinline__ ull add2(ull a, ull b) {
    ull r; asm("add.rn.f32x2 %0, %1, %2;" : "=l"(r) : "l"(a), "l"(b)); return r;
}
__device__ __forceinline__ float2 unpack2(ull v) {
    float2 r; asm("mov.b64 {%0,%1}, %2;" : "=f"(r.x), "=f"(r.y) : "l"(v)); return r;
}
__device__ __forceinline__ uint h2u(__half2 h) { return *reinterpret_cast<uint*>(&h); }
__device__ __forceinline__ __half2 u2h(uint u) { return *reinterpret_cast<__half2*>(&u); }

// ---------------------------------------------------------------------------
// P[N,128] = X[N,128] @ W[128,128] (+bias), stored fp16. blockIdx.y selects.
// f32x2 mainloop: W staged in smem as k-pair packed ull[64][128]
// (lo = W[2kp][c], hi = W[2kp+1][c]); accumulators hold (even-k, odd-k)
// partial sums, summed in the epilogue (exact fp32).
__global__ __launch_bounds__(256, 2) void gemm_x128(
    const float* __restrict__ X0, const float* __restrict__ X1,
    const float* __restrict__ W1, const float* __restrict__ b1,
    int N0, int N1)
{
    extern __shared__ char smraw[];
    ull*   ws2 = (ull*)smraw;                       // [64][128] pairs, 64 KB
    float* xs  = (float*)(smraw + 64 * 128 * 8);    // [64][132], 33.8 KB
    const int t = threadIdx.x;
    const int sel = blockIdx.y;
    const float* __restrict__ X = sel ? X1 : X0;
    const float* __restrict__ W = sel ? (W1 + 128 * 128) : W1;
    uint* __restrict__ P = sel ? g_Pa : g_Pn;
    const int N = sel ? N1 : N0;
    const int row0 = blockIdx.x * 64;
    if (row0 >= N) return;

    // stage W as k-pair packed ull (coalesced row reads)
    for (int i = t; i < 64 * 128; i += 256) {
        int kp = i >> 7, c = i & 127;
        ws2[i] = pack2(W[(2 * kp) * 128 + c], W[(2 * kp + 1) * 128 + c]);
    }
    // stage X tile: 64 rows x 32 float4
    for (int i = t; i < 64 * 32; i += 256) {
        int r = i >> 5, c4 = i & 31;
        float4 v = make_float4(0.f, 0.f, 0.f, 0.f);
        int gr = row0 + r;
        if (gr < N) v = ((const float4*)X)[(size_t)gr * 32 + c4];
        float* xr = xs + r * 132 + c4 * 4;
        xr[0] = v.x; xr[1] = v.y; xr[2] = v.z; xr[3] = v.w;
    }
    __syncthreads();

    const int c  = (t & 31) * 4;     // output cols c..c+3
    const int r0 = (t >> 5) * 8;     // output rows r0..r0+7
    ull acc[8][4];
#pragma unroll
    for (int i = 0; i < 8; i++)
#pragma unroll
        for (int j = 0; j < 4; j++) acc[i][j] = 0ull;

#pragma unroll 4
    for (int kp = 0; kp < 64; kp++) {
        ull b2[4];
        {
            ulonglong2 w0 = *(const ulonglong2*)(ws2 + kp * 128 + c);
            ulonglong2 w1 = *(const ulonglong2*)(ws2 + kp * 128 + c + 2);
            b2[0] = w0.x; b2[1] = w0.y; b2[2] = w1.x; b2[3] = w1.y;
        }
#pragma unroll
        for (int i = 0; i < 8; i++) {
            ull a2 = *(const ull*)(xs + (r0 + i) * 132 + kp * 2); // broadcast LDS.64
            ffma2(acc[i][0], a2, b2[0]);
            ffma2(acc[i][1], a2, b2[1]);
            ffma2(acc[i][2], a2, b2[2]);
            ffma2(acc[i][3], a2, b2[3]);
        }
    }

    float bvx = 0.f, bvy = 0.f, bvz = 0.f, bvw = 0.f;
    if (sel) { float4 bb = *(const float4*)(b1 + c);
               bvx = bb.x; bvy = bb.y; bvz = bb.z; bvw = bb.w; }
#pragma unroll
    for (int i = 0; i < 8; i++) {
        int gr = row0 + r0 + i;
        if (gr < N) {
            float2 u0 = unpack2(acc[i][0]), u1 = unpack2(acc[i][1]);
            float2 u2 = unpack2(acc[i][2]), u3 = unpack2(acc[i][3]);
            uint p01 = h2u(__floats2half2_rn(u0.x + u0.y + bvx, u1.x + u1.y + bvy));
            uint p23 = h2u(__floats2half2_rn(u2.x + u2.y + bvz, u3.x + u3.y + bvw));
            *(uint2*)(P + (size_t)gr * 64 + (c >> 1)) = make_uint2(p01, p23);
        }
    }
}

// ---------------------------------------------------------------------------
// Fused edge + zero(cols 128..256) + own(cols 256..264).
// Block 256 = 2 agents x 16 edges x 8 threads. Thread (eg,j) handles
// k = 4(j+8i)+q; gathers are uint2 (4 halves, 8-lane group covers 64B).
// Weight smem: injective stride-36 layout off(4K+q,c)=K*36+q*8+c (R7-verified).
// Index dtype detected inline from eslot word pattern (uniform branch).
__global__ __launch_bounds__(256) void edge_fused_kernel(
    const float* __restrict__ W2, const float* __restrict__ b2,
    const float* __restrict__ Wa, const float* __restrict__ ba,
    const float* __restrict__ xa,
    const void* __restrict__ esrc, const void* __restrict__ edst,
    const void* __restrict__ eslot,
    float* __restrict__ out, int E, int Na)
{
    __shared__ float w2s[32 * 36];
    __shared__ float was[32 * 36];

    const int t  = threadIdx.x;
    const int g  = t >> 7;
    const int at = t & 127;
    const int eg = at >> 3;
    const int j  = at & 7;

    for (int i = t; i < 1024; i += 256) {
        int k = i >> 3, c = i & 7;
        int off = (k >> 2) * 36 + (k & 3) * 8 + c;
        w2s[off] = W2[i];
        was[off] = Wa[i];
    }
    __syncthreads();

    const int idx64 = (((const int*)eslot)[1] != 1);   // int64: hi-word of slot0
    const int agent = blockIdx.x * 2 + g;
    const bool agent_ok = (agent < Na);

    if (agent_ok)
        out[(size_t)agent * OUT_COLS + 128 + at] = 0.f;

    const int e = agent * 16 + eg;
    if (e < E) {
        int src, dst, slot;
        if (idx64) {   // values < 2^31, read little-endian low words
            src  = ((const int*)esrc)[2 * e];
            dst  = ((const int*)edst)[2 * e];
            slot = ((const int*)eslot)[2 * e];
        } else {
            src  = ((const int*)esrc)[e];
            dst  = ((const int*)edst)[e];
            slot = ((const int*)eslot)[e];
        }

        const uint2* __restrict__ pr = (const uint2*)(g_Pn + (size_t)src * 64);
        const uint2* __restrict__ ar = (const uint2*)(g_Pa + (size_t)dst * 64);
        uint2 araw[4], craw[4];
#pragma unroll
        for (int i = 0; i < 4; i++) { araw[i] = pr[j + 8 * i]; craw[i] = ar[j + 8 * i]; }

        const __half2 z2 = __floats2half2_rn(0.f, 0.f);
        ull acc[4] = {0ull, 0ull, 0ull, 0ull};
#pragma unroll
        for (int i = 0; i < 4; i++) {
            __half2 h0 = __hmax2(__hadd2(u2h(araw[i].x), u2h(craw[i].x)), z2);
            __half2 h1 = __hmax2(__hadd2(u2h(araw[i].y), u2h(craw[i].y)), z2);
            float2 f0 = __half22float2(h0);
            float2 f1 = __half22float2(h1);
            const float* wb = w2s + (j + 8 * i) * 36;
#pragma unroll
            for (int q = 0; q < 4; q++) {
                float v = (q == 0) ? f0.x : (q == 1) ? f0.y : (q == 2) ? f1.x : f1.y;
                ull vv = pack2(v, v);
                const ull* w = (const ull*)(wb + q * 8);
                ffma2(acc[0], vv, w[0]);
                ffma2(acc[1], vv, w[1]);
                ffma2(acc[2], vv, w[2]);
                ffma2(acc[3], vv, w[3]);
            }
        }
#pragma unroll
        for (int d = 1; d < 8; d <<= 1) {
#pragma unroll
            for (int p = 0; p < 4; p++)
                acc[p] = add2(acc[p], __shfl_xor_sync(0xffffffffu, acc[p], d));
        }
        float2 u = unpack2(acc[j >> 1]);
        float s = ((j & 1) ? u.y : u.x) + __ldg(b2 + j);
        out[(size_t)dst * OUT_COLS + slot * 8 + j] = s;
    }

    // own score (fp32 inputs)
    if (eg == 0 && agent_ok) {
        const float4* __restrict__ xr = (const float4*)(xa + (size_t)agent * 128);
        float4 a4[4];
#pragma unroll
        for (int i = 0; i < 4; i++) a4[i] = xr[j + 8 * i];

        ull acc[4] = {0ull, 0ull, 0ull, 0ull};
#pragma unroll
        for (int i = 0; i < 4; i++) {
            const float* wb = was + (j + 8 * i) * 36;
#pragma unroll
            for (int q = 0; q < 4; q++) {
                float v = (q == 0) ? a4[i].x : (q == 1) ? a4[i].y
                        : (q == 2) ? a4[i].z : a4[i].w;
                ull vv = pack2(v, v);
                const ull* w = (const ull*)(wb + q * 8);
                ffma2(acc[0], vv, w[0]);
                ffma2(acc[1], vv, w[1]);
                ffma2(acc[2], vv, w[2]);
                ffma2(acc[3], vv, w[3]);
            }
        }
#pragma unroll
        for (int d = 1; d < 8; d <<= 1) {
#pragma unroll
            for (int p = 0; p < 4; p++)
                acc[p] = add2(acc[p], __shfl_xor_sync(0x000000ffu, acc[p], d));
        }
        float2 u = unpack2(acc[j >> 1]);
        float s = ((j & 1) ? u.y : u.x) + __ldg(ba + j);
        out[(size_t)agent * OUT_COLS + 256 + j] = s;
    }
}

// ---------------------------------------------------------------------------
extern "C" void kernel_launch(void* const* d_in, const int* in_sizes, int n_in,
                              void* d_out, int out_size)
{
    const float* x_nbr   = (const float*)d_in[0];
    const float* x_agent = (const float*)d_in[1];
    const float* W1      = (const float*)d_in[2];
    const float* b1      = (const float*)d_in[3];
    const float* W2      = (const float*)d_in[4];
    const float* b2      = (const float*)d_in[5];
    const float* Wa      = (const float*)d_in[6];
    const float* ba      = (const float*)d_in[7];
    const void*  esrc    = d_in[8];
    const void*  edst    = d_in[9];
    const void*  eslot   = d_in[10];

    int Nn = in_sizes[0] / HID;
    int Na = in_sizes[1] / HID;
    int E  = in_sizes[8];
    float* out = (float*)d_out;

    const int gemm_smem = 64 * 128 * 8 + 64 * 132 * 4;   // 99328 B
    cudaFuncSetAttribute(gemm_x128, cudaFuncAttributeMaxDynamicSharedMemorySize,
                         gemm_smem);

    int Nmax = Nn > Na ? Nn : Na;
    dim3 ggrid((Nmax + 63) / 64, 2);
    gemm_x128<<<ggrid, 256, gemm_smem>>>(x_nbr, x_agent, W1, b1, Nn, Na);

    int units = (E + 15) / 16;
    if (Na > units) units = Na;
    int blocks = (units + 1) / 2;
    edge_fused_kernel<<<blocks, 256>>>(W2, b2, Wa, ba, x_agent,
                                       esrc, edst, eslot, out, E, Na);
}

// round 12
// speedup vs baseline: 1.5415x; 1.3846x over previous
#include <cuda_runtime.h>
#include <cuda_fp16.h>

#define HID 128
#define OUT_COLS 264
#define MAXN 50176

typedef unsigned long long ull;
typedef unsigned int uint;

// fp16 storage of projected node features (half2 packed as uint)
__device__ uint g_Pn[(size_t)MAXN * 64];   // x_nbr  @ W1[:128]
__device__ uint g_Pa[(size_t)MAXN * 64];   // x_agent@ W1[128:] + b1

// ---- packed fp32x2 helpers (sm_103a) --------------------------------------
__device__ __forceinline__ ull pack2(float lo, float hi) {
    ull r; asm("mov.b64 %0, {%1,%2};" : "=l"(r) : "f"(lo), "f"(hi)); return r;
}
__device__ __forceinline__ void ffma2(ull& d, ull a, ull b) {
    asm("fma.rn.f32x2 %0, %1, %2, %0;" : "+l"(d) : "l"(a), "l"(b));
}
__device__ __forceinline__ ull add2(ull a, ull b) {
    ull r; asm("add.rn.f32x2 %0, %1, %2;" : "=l"(r) : "l"(a), "l"(b)); return r;
}
__device__ __forceinline__ float2 unpack2(ull v) {
    float2 r; asm("mov.b64 {%0,%1}, %2;" : "=f"(r.x), "=f"(r.y) : "l"(v)); return r;
}
__device__ __forceinline__ uint h2u(__half2 h) { return *reinterpret_cast<uint*>(&h); }
__device__ __forceinline__ __half2 u2h(uint u) { return *reinterpret_cast<__half2*>(&u); }

// ---------------------------------------------------------------------------
// P[N,128] = X[N,128] @ W[128,128] (+bias), stored fp16. blockIdx.y selects.
// f32x2 mainloop (unchanged from R11).
__global__ __launch_bounds__(256, 2) void gemm_x128(
    const float* __restrict__ X0, const float* __restrict__ X1,
    const float* __restrict__ W1, const float* __restrict__ b1,
    int N0, int N1)
{
    extern __shared__ char smraw[];
    ull*   ws2 = (ull*)smraw;                       // [64][128] pairs
    float* xs  = (float*)(smraw + 64 * 128 * 8);    // [64][132]
    const int t = threadIdx.x;
    const int sel = blockIdx.y;
    const float* __restrict__ X = sel ? X1 : X0;
    const float* __restrict__ W = sel ? (W1 + 128 * 128) : W1;
    uint* __restrict__ P = sel ? g_Pa : g_Pn;
    const int N = sel ? N1 : N0;
    const int row0 = blockIdx.x * 64;
    if (row0 >= N) return;

    for (int i = t; i < 64 * 128; i += 256) {
        int kp = i >> 7, c = i & 127;
        ws2[i] = pack2(W[(2 * kp) * 128 + c], W[(2 * kp + 1) * 128 + c]);
    }
    for (int i = t; i < 64 * 32; i += 256) {
        int r = i >> 5, c4 = i & 31;
        float4 v = make_float4(0.f, 0.f, 0.f, 0.f);
        int gr = row0 + r;
        if (gr < N) v = ((const float4*)X)[(size_t)gr * 32 + c4];
        float* xr = xs + r * 132 + c4 * 4;
        xr[0] = v.x; xr[1] = v.y; xr[2] = v.z; xr[3] = v.w;
    }
    __syncthreads();

    const int c  = (t & 31) * 4;
    const int r0 = (t >> 5) * 8;
    ull acc[8][4];
#pragma unroll
    for (int i = 0; i < 8; i++)
#pragma unroll
        for (int j = 0; j < 4; j++) acc[i][j] = 0ull;

#pragma unroll 4
    for (int kp = 0; kp < 64; kp++) {
        ull b2v[4];
        {
            ulonglong2 w0 = *(const ulonglong2*)(ws2 + kp * 128 + c);
            ulonglong2 w1 = *(const ulonglong2*)(ws2 + kp * 128 + c + 2);
            b2v[0] = w0.x; b2v[1] = w0.y; b2v[2] = w1.x; b2v[3] = w1.y;
        }
#pragma unroll
        for (int i = 0; i < 8; i++) {
            ull a2 = *(const ull*)(xs + (r0 + i) * 132 + kp * 2);
            ffma2(acc[i][0], a2, b2v[0]);
            ffma2(acc[i][1], a2, b2v[1]);
            ffma2(acc[i][2], a2, b2v[2]);
            ffma2(acc[i][3], a2, b2v[3]);
        }
    }

    float bvx = 0.f, bvy = 0.f, bvz = 0.f, bvw = 0.f;
    if (sel) { float4 bb = *(const float4*)(b1 + c);
               bvx = bb.x; bvy = bb.y; bvz = bb.z; bvw = bb.w; }
#pragma unroll
    for (int i = 0; i < 8; i++) {
        int gr = row0 + r0 + i;
        if (gr < N) {
            float2 u0 = unpack2(acc[i][0]), u1 = unpack2(acc[i][1]);
            float2 u2 = unpack2(acc[i][2]), u3 = unpack2(acc[i][3]);
            uint p01 = h2u(__floats2half2_rn(u0.x + u0.y + bvx, u1.x + u1.y + bvy));
            uint p23 = h2u(__floats2half2_rn(u2.x + u2.y + bvz, u3.x + u3.y + bvw));
            *(uint2*)(P + (size_t)gr * 64 + (c >> 1)) = make_uint2(p01, p23);
        }
    }
}

// ---------------------------------------------------------------------------
// Two-phase fused edge kernel. Block = 256 threads, 8 agents = 128 edges.
// Phase 1: gather Pn[src]+Pa[dst], relu, stage half2 into v_sm with XOR
//   swizzle pos(u) = u ^ (2*(el&15))  (bit0 preserved -> 8B stores legal).
// Phase 2: 2 threads/edge (4 cols each); weights read via BROADCAST LDS
//   (all lanes same kp address), activations conflict-free via swizzle.
// Plus: zero out[:,128:256) and own-score out[:,256:264) for the block's agents.
__global__ __launch_bounds__(256) void edge_fused_kernel(
    const float* __restrict__ W2, const float* __restrict__ b2,
    const float* __restrict__ Wa, const float* __restrict__ ba,
    const float* __restrict__ xa,
    const void* __restrict__ esrc, const void* __restrict__ edst,
    const void* __restrict__ eslot,
    float* __restrict__ out, int E, int Na)
{
    __shared__ uint  v_sm[128 * 64];     // 32 KB
    __shared__ ull   w2p[64 * 8];        // 4 KB  (even,odd) k-pair packed W2
    __shared__ float was[32 * 36];       // own-score weights, stride-36 layout
    __shared__ float b2s[8], bas[8];

    const int t = threadIdx.x;

    for (int i = t; i < 512; i += 256) {
        int kp = i >> 3, c = i & 7;
        w2p[i] = pack2(W2[(2 * kp) * 8 + c], W2[(2 * kp + 1) * 8 + c]);
    }
    for (int i = t; i < 1024; i += 256) {
        int k = i >> 3, c = i & 7;
        was[(k >> 2) * 36 + (k & 3) * 8 + c] = Wa[i];
    }
    if (t < 8) { b2s[t] = b2[t]; bas[t] = ba[t]; }

    const int idx64 = (((const int*)eslot)[1] != 1);
    const int e0 = blockIdx.x * 128;
    const __half2 z2 = __floats2half2_rn(0.f, 0.f);

    // ---- phase 1: gather + relu -> v_sm -----------------------------------
    {
        const int j  = t & 7;            // chunk id (16B each, half-row per 8 lanes)
        const int eb = t >> 3;           // 0..31
#pragma unroll
        for (int s = 0; s < 4; s++) {
            int el = eb + 32 * s;
            int eg = e0 + el;
            if (eg < E) {
                int src, dst;
                if (idx64) { src = ((const int*)esrc)[2 * eg];
                             dst = ((const int*)edst)[2 * eg]; }
                else       { src = ((const int*)esrc)[eg];
                             dst = ((const int*)edst)[eg]; }
                const uint4* pr = (const uint4*)(g_Pn + (size_t)src * 64);
                const uint4* ar = (const uint4*)(g_Pa + (size_t)dst * 64);
                uint4 A0 = pr[j], A1 = pr[j + 8];
                uint4 C0 = ar[j], C1 = ar[j + 8];
                uint4 V0, V1;
                V0.x = h2u(__hmax2(__hadd2(u2h(A0.x), u2h(C0.x)), z2));
                V0.y = h2u(__hmax2(__hadd2(u2h(A0.y), u2h(C0.y)), z2));
                V0.z = h2u(__hmax2(__hadd2(u2h(A0.z), u2h(C0.z)), z2));
                V0.w = h2u(__hmax2(__hadd2(u2h(A0.w), u2h(C0.w)), z2));
                V1.x = h2u(__hmax2(__hadd2(u2h(A1.x), u2h(C1.x)), z2));
                V1.y = h2u(__hmax2(__hadd2(u2h(A1.y), u2h(C1.y)), z2));
                V1.z = h2u(__hmax2(__hadd2(u2h(A1.z), u2h(C1.z)), z2));
                V1.w = h2u(__hmax2(__hadd2(u2h(A1.w), u2h(C1.w)), z2));

                const int xr = 2 * (el & 15);
                uint* vb = v_sm + el * 64;
                int q0 = (4 * j) ^ xr;          // even -> 8B aligned
                *(uint2*)(vb + q0)        = make_uint2(V0.x, V0.y);
                *(uint2*)(vb + (q0 ^ 2))  = make_uint2(V0.z, V0.w);
                int q1 = q0 + 32;               // (4j+32)^xr, bit5 untouched
                *(uint2*)(vb + q1)        = make_uint2(V1.x, V1.y);
                *(uint2*)(vb + (q1 ^ 2))  = make_uint2(V1.z, V1.w);
            }
        }
    }
    __syncthreads();

    // ---- phase 2: matvec, 2 threads per edge ------------------------------
    {
        const int el = t >> 1;           // 0..127
        const int h  = t & 1;            // col half: cols 4h..4h+3
        const int eg = e0 + el;
        if (eg < E) {
            int dst, slot;
            if (idx64) { dst  = ((const int*)edst)[2 * eg];
                         slot = ((const int*)eslot)[2 * eg]; }
            else       { dst  = ((const int*)edst)[eg];
                         slot = ((const int*)eslot)[eg]; }

            const int xr = 2 * (el & 15);
            const uint* vb = v_sm + el * 64;
            ull a0 = 0ull, a1 = 0ull, a2 = 0ull, a3 = 0ull;
#pragma unroll 8
            for (int kp = 0; kp < 64; kp++) {
                uint vu = vb[kp ^ xr];                    // conflict-free LDS.32
                float2 f = __half22float2(u2h(vu));
                ull vv = pack2(f.x, f.y);
                const ull* w = w2p + kp * 8 + 4 * h;      // broadcast LDS
                ulonglong2 wA = *(const ulonglong2*)w;
                ulonglong2 wB = *(const ulonglong2*)(w + 2);
                ffma2(a0, vv, wA.x); ffma2(a1, vv, wA.y);
                ffma2(a2, vv, wB.x); ffma2(a3, vv, wB.y);
            }
            float2 u0 = unpack2(a0), u1 = unpack2(a1);
            float2 u2 = unpack2(a2), u3 = unpack2(a3);
            float4 r = make_float4(u0.x + u0.y + b2s[4 * h],
                                   u1.x + u1.y + b2s[4 * h + 1],
                                   u2.x + u2.y + b2s[4 * h + 2],
                                   u3.x + u3.y + b2s[4 * h + 3]);
            *(float4*)(out + (size_t)dst * OUT_COLS + slot * 8 + 4 * h) = r;
        }
    }

    // ---- zero out[:,128:256) for this block's 8 agents --------------------
    const int ag0 = blockIdx.x * 8;
#pragma unroll
    for (int i = t; i < 1024; i += 256) {
        int a = ag0 + (i >> 7);
        if (a < Na) out[(size_t)a * OUT_COLS + 128 + (i & 127)] = 0.f;
    }

    // ---- own scores: threads 0..63, 8 threads per agent -------------------
    if (t < 64) {
        int a  = ag0 + (t >> 3);
        int jj = t & 7;
        if (a < Na) {
            const float4* xr4 = (const float4*)(xa + (size_t)a * 128);
            float4 a4[4];
#pragma unroll
            for (int i = 0; i < 4; i++) a4[i] = xr4[jj + 8 * i];

            ull acc[4] = {0ull, 0ull, 0ull, 0ull};
#pragma unroll
            for (int i = 0; i < 4; i++) {
                const float* wb = was + (jj + 8 * i) * 36;
#pragma unroll
                for (int q = 0; q < 4; q++) {
                    float v = (q == 0) ? a4[i].x : (q == 1) ? a4[i].y
                            : (q == 2) ? a4[i].z : a4[i].w;
                    ull vv = pack2(v, v);
                    const ull* w = (const ull*)(wb + q * 8);
                    ffma2(acc[0], vv, w[0]);
                    ffma2(acc[1], vv, w[1]);
                    ffma2(acc[2], vv, w[2]);
                    ffma2(acc[3], vv, w[3]);
                }
            }
#pragma unroll
            for (int d = 1; d < 8; d <<= 1) {
#pragma unroll
                for (int p = 0; p < 4; p++)
                    acc[p] = add2(acc[p], __shfl_xor_sync(0xffffffffu, acc[p], d));
            }
            float2 u = unpack2(acc[jj >> 1]);
            float s = ((jj & 1) ? u.y : u.x) + bas[jj];
            out[(size_t)a * OUT_COLS + 256 + jj] = s;
        }
    }
}

// ---------------------------------------------------------------------------
extern "C" void kernel_launch(void* const* d_in, const int* in_sizes, int n_in,
                              void* d_out, int out_size)
{
    const float* x_nbr   = (const float*)d_in[0];
    const float* x_agent = (const float*)d_in[1];
    const float* W1      = (const float*)d_in[2];
    const float* b1      = (const float*)d_in[3];
    const float* W2      = (const float*)d_in[4];
    const float* b2      = (const float*)d_in[5];
    const float* Wa      = (const float*)d_in[6];
    const float* ba      = (const float*)d_in[7];
    const void*  esrc    = d_in[8];
    const void*  edst    = d_in[9];
    const void*  eslot   = d_in[10];

    int Nn = in_sizes[0] / HID;
    int Na = in_sizes[1] / HID;
    int E  = in_sizes[8];
    float* out = (float*)d_out;

    const int gemm_smem = 64 * 128 * 8 + 64 * 132 * 4;   // 99328 B
    cudaFuncSetAttribute(gemm_x128, cudaFuncAttributeMaxDynamicSharedMemorySize,
                         gemm_smem);

    int Nmax = Nn > Na ? Nn : Na;
    dim3 ggrid((Nmax + 63) / 64, 2);
    gemm_x128<<<ggrid, 256, gemm_smem>>>(x_nbr, x_agent, W1, b1, Nn, Na);

    int blocks_e = (E + 127) / 128;
    int blocks_a = (Na + 7) / 8;
    int blocks = blocks_e > blocks_a ? blocks_e : blocks_a;
    edge_fused_kernel<<<blocks, 256>>>(W2, b2, Wa, ba, x_agent,
                                       esrc, edst, eslot, out, E, Na);
}